// round 12
// baseline (speedup 1.0000x reference)
#include <cuda_runtime.h>
#include <cuda_fp16.h>
#include <cstdint>

#define NELEM 16777216            // 4*16*2048*128

// ---------------- global scratch (allocation-free) ----------------
__device__ __align__(16) uint32_t g_mask[2048 * 64];
__device__ __align__(16) __half g_qh[NELEM];
__device__ __align__(16) __half g_kh[NELEM];
__device__ __align__(16) __half g_vh[NELEM];

// ---------------- smem layout: 5 tile buffers, ROWH pad for conflict-free ldmatrix
#define ROWH 136
#define BUFB (128 * ROWH * 2)     // 34816 B per 128x128 fp16 tile
#define OQ_B  (0 * BUFB)
#define OK0_B (1 * BUFB)
#define OK1_B (2 * BUFB)
#define OV0_B (3 * BUFB)
#define OV1_B (4 * BUFB)
#define SMEM_B (5 * BUFB)         // 174080 B

// ---------------- helpers ----------------
__device__ __forceinline__ uint32_t smem_u32(const void* p) {
    uint32_t a;
    asm("{ .reg .u64 t; cvta.to.shared.u64 t, %1; cvt.u32.u64 %0, t; }" : "=r"(a) : "l"(p));
    return a;
}
__device__ __forceinline__ float ex2(float x) {
    float y; asm("ex2.approx.ftz.f32 %0, %1;" : "=f"(y) : "f"(x)); return y;
}
__device__ __forceinline__ uint32_t packh2(float x0, float x1) {
    __half2 h = __floats2half2_rn(x0, x1);
    return *reinterpret_cast<uint32_t*>(&h);
}
__device__ __forceinline__ void mma_f16(float* c, const uint32_t* a, const uint32_t* b) {
    asm volatile("mma.sync.aligned.m16n8k16.row.col.f32.f16.f16.f32 "
        "{%0,%1,%2,%3}, {%4,%5,%6,%7}, {%8,%9}, {%0,%1,%2,%3};"
        : "+f"(c[0]), "+f"(c[1]), "+f"(c[2]), "+f"(c[3])
        : "r"(a[0]), "r"(a[1]), "r"(a[2]), "r"(a[3]), "r"(b[0]), "r"(b[1]));
}
#define LDSM_X4(r, addr) \
    asm volatile("ldmatrix.sync.aligned.m8n8.x4.shared.b16 {%0,%1,%2,%3}, [%4];" \
        : "=r"((r)[0]), "=r"((r)[1]), "=r"((r)[2]), "=r"((r)[3]) : "r"(addr))
#define LDSM_X4T(r, addr) \
    asm volatile("ldmatrix.sync.aligned.m8n8.x4.trans.shared.b16 {%0,%1,%2,%3}, [%4];" \
        : "=r"((r)[0]), "=r"((r)[1]), "=r"((r)[2]), "=r"((r)[3]) : "r"(addr))
__device__ __forceinline__ void cpa16(uint32_t dst, const void* src) {
    asm volatile("cp.async.cg.shared.global [%0], [%1], 16;" :: "r"(dst), "l"(src) : "memory");
}
#define CP_COMMIT() asm volatile("cp.async.commit_group;" ::: "memory")
#define CP_WAIT0()  asm volatile("cp.async.wait_group 0;" ::: "memory")

// padded byte offset inside a buffer for data uint4 index i (row = i>>4, col16 = i&15)
__device__ __forceinline__ uint32_t pad_off(int i) {
    return (uint32_t)(((i >> 4) * 17 + (i & 15)) * 16);
}

// ---------------- prep kernels ----------------
__global__ void pack_mask_kernel(const int* __restrict__ mask) {
    int w = blockIdx.x * blockDim.x + threadIdx.x;
    const int4* m4 = reinterpret_cast<const int4*>(mask) + (size_t)w * 8;
    uint32_t b = 0;
#pragma unroll
    for (int i = 0; i < 8; i++) {
        int4 v = m4[i];
        b |= (uint32_t)(v.x != 0) << (i * 4)     | (uint32_t)(v.y != 0) << (i * 4 + 1)
           | (uint32_t)(v.z != 0) << (i * 4 + 2) | (uint32_t)(v.w != 0) << (i * 4 + 3);
    }
    g_mask[w] = b;
}
// fused Q/K/V fp32 -> fp16 conversion; blockIdx.y selects tensor
__global__ void prep_qkv_kernel(const float4* __restrict__ q,
                                const float4* __restrict__ k,
                                const float4* __restrict__ v) {
    const float CS = 1.4426950408889634f / 11.313708498984761f;  // log2(e)/sqrt(128)
    int i = blockIdx.x * 256 + threadIdx.x;
    int sel = blockIdx.y;
    const float4* src = (sel == 0) ? q : (sel == 1) ? k : v;
    float sc = (sel == 0) ? CS : 1.0f;
    __half* dst = (sel == 0) ? g_qh : (sel == 1) ? g_kh : g_vh;
    float4 x = src[i];
    reinterpret_cast<uint2*>(dst)[i] = make_uint2(packh2(x.x * sc, x.y * sc),
                                                  packh2(x.z * sc, x.w * sc));
}

// ---------------- main kernel: grid(16, 64), 256 threads (8 warps) ----------------
__global__ void __launch_bounds__(256, 1)
flash_mma_kernel(float* __restrict__ Out)
{
    extern __shared__ __align__(16) char smp[];
    const uint32_t sbase = smem_u32(smp);
    const int tid = threadIdx.x, w = tid >> 5, lane = tid & 31;
    const int bh = blockIdx.y, qb = blockIdx.x;

    const size_t TILE4 = 2048;                          // uint4 per 128x128 fp16 tile
    const size_t hbase4 = (size_t)bh * (TILE4 * 16);
    const size_t qtile4 = hbase4 + (size_t)qb * TILE4;

    const uint4* gq4 = reinterpret_cast<const uint4*>(g_qh);
    const uint4* gk4 = reinterpret_cast<const uint4*>(g_kh);
    const uint4* gv4 = reinterpret_cast<const uint4*>(g_vh);

    // ---- prologue: Q, K(0), V(0) via cp.async ----
    for (int i = tid; i < 2048; i += 256) {
        uint32_t po = pad_off(i);
        cpa16(sbase + OQ_B  + po, gq4 + qtile4 + i);
        cpa16(sbase + OK0_B + po, gk4 + hbase4 + i);
        cpa16(sbase + OV0_B + po, gv4 + hbase4 + i);
    }
    CP_COMMIT();

    float sacc[16][4], oacc[16][4];
    float lsum0 = 0.f, lsum1 = 0.f;
#pragma unroll
    for (int i = 0; i < 16; i++) { oacc[i][0] = oacc[i][1] = oacc[i][2] = oacc[i][3] = 0.f; }

    // per-thread ldmatrix base byte addresses (mapping validated R7-R11)
    const uint32_t aQ  = sbase + OQ_B + (w * 16 + (lane & 15)) * 272 + ((lane & 16) ? 16 : 0);
    const uint32_t bK  = ((lane >> 4) * 8 + (lane & 7)) * 272 + ((lane & 8) ? 16 : 0);
    const uint32_t vVb = (lane & 15) * 272 + ((lane >> 4) ? 16 : 0);

    const int rloc0 = w * 16 + (lane >> 2);
    const int shf = (lane & 3) * 2;
    const uint32_t* mrow0 = g_mask + (size_t)(qb * 128 + rloc0) * 64;
    const uint32_t* mrow1 = mrow0 + 8 * 64;

    CP_WAIT0();
    __syncthreads();

    for (int t = 0; t < 16; t++) {
        const uint32_t kcur = sbase + ((t & 1) ? OK1_B : OK0_B);
        const uint32_t vcur = sbase + ((t & 1) ? OV1_B : OV0_B);
        if (t < 15) {   // prefetch next K/V into alternate buffers
            const uint32_t knxt = sbase + ((t & 1) ? OK0_B : OK1_B);
            const uint32_t vnxt = sbase + ((t & 1) ? OV0_B : OV1_B);
            const size_t toff = hbase4 + (size_t)(t + 1) * TILE4;
            for (int i = tid; i < 2048; i += 256) {
                uint32_t po = pad_off(i);
                cpa16(knxt + po, gk4 + toff + i);
                cpa16(vnxt + po, gv4 + toff + i);
            }
        }
        CP_COMMIT();

        // ---- mask words for this tile ----
        uint32_t mq0[4], mq1[4];
#pragma unroll
        for (int d_ = 0; d_ < 4; d_++) {
            mq0[d_] = __ldg(mrow0 + t * 4 + d_);
            mq1[d_] = __ldg(mrow1 + t * 4 + d_);
        }

        // ---- S = Q Kᵀ : depth-4 (group) double-buffered B + Q chunk buffer ----
        // it = kt*8 + j2 ; group g covers it in [4g, 4g+4): kt = g>>1, j2 = (g&1)*4+u
#pragma unroll
        for (int i = 0; i < 16; i++) { sacc[i][0] = sacc[i][1] = sacc[i][2] = sacc[i][3] = 0.f; }
        {
            uint32_t Bb[2][4][4];
            uint32_t Qb[2][4];
            LDSM_X4(Qb[0], aQ);                           // Q chunk 0
#pragma unroll
            for (int u = 0; u < 4; u++) LDSM_X4(Bb[0][u], kcur + bK + u * 4352);  // g=0
#pragma unroll
            for (int g = 0; g < 16; g++) {
                const int cur = g & 1, nxt = cur ^ 1;
                const int kt = g >> 1;
                if (g < 15) {                              // prefetch group g+1 B-frags
#pragma unroll
                    for (int u = 0; u < 4; u++) {
                        const int it1 = (g + 1) * 4 + u;
                        LDSM_X4(Bb[nxt][u], kcur + bK + ((it1 & 7) * 4352) + ((it1 >> 3) * 32));
                    }
                    if (g & 1) LDSM_X4(Qb[(kt + 1) & 1], aQ + (kt + 1) * 32); // next Q chunk
                }
#pragma unroll
                for (int u = 0; u < 4; u++) {
                    const int j2 = (g & 1) * 4 + u;
                    mma_f16(sacc[2 * j2],     Qb[kt & 1], Bb[cur][u]);
                    mma_f16(sacc[2 * j2 + 1], Qb[kt & 1], Bb[cur][u] + 2);
                }
            }
        }

        // ---- fused softmax + PV : depth-4 double-buffered B, AH double-buffered ----
        {
            uint32_t Bb[2][4][4];
            uint32_t AH[2][4];
#pragma unroll
            for (int u = 0; u < 4; u++) LDSM_X4T(Bb[0][u], vcur + vVb + u * 32);  // kt=0, j2=u
            // AH chunk 0
#pragma unroll
            for (int pk = 0; pk < 1; pk++) {
                const int n0 = 0, n1 = 1;
                uint32_t a0 = mq0[0] >> (shf);
                uint32_t a1 = mq1[0] >> (shf);
                uint32_t c0 = mq0[0] >> (8 + shf);
                uint32_t c1 = mq1[0] >> (8 + shf);
                float p0 = (a0 & 1u) ? ex2(sacc[n0][0]) : 0.f;
                float p1 = (a0 & 2u) ? ex2(sacc[n0][1]) : 0.f;
                float p2 = (a1 & 1u) ? ex2(sacc[n0][2]) : 0.f;
                float p3 = (a1 & 2u) ? ex2(sacc[n0][3]) : 0.f;
                float p4 = (c0 & 1u) ? ex2(sacc[n1][0]) : 0.f;
                float p5 = (c0 & 2u) ? ex2(sacc[n1][1]) : 0.f;
                float p6 = (c1 & 1u) ? ex2(sacc[n1][2]) : 0.f;
                float p7 = (c1 & 2u) ? ex2(sacc[n1][3]) : 0.f;
                lsum0 += (p0 + p1) + (p4 + p5);
                lsum1 += (p2 + p3) + (p6 + p7);
                AH[0][0] = packh2(p0, p1); AH[0][1] = packh2(p2, p3);
                AH[0][2] = packh2(p4, p5); AH[0][3] = packh2(p6, p7);
            }
#pragma unroll
            for (int g = 0; g < 16; g++) {
                const int cur = g & 1, nxt = cur ^ 1;
                const int kt = g >> 1;
                if (g < 15) {                              // prefetch group g+1 B-frags
#pragma unroll
                    for (int u = 0; u < 4; u++) {
                        const int it1 = (g + 1) * 4 + u;
                        LDSM_X4T(Bb[nxt][u], vcur + vVb + ((it1 >> 3) * 4352) + ((it1 & 7) * 32));
                    }
                }
                if ((g & 1) && g < 15) {                   // AH for chunk kt+1 during odd group
                    const int n0 = 2 * (kt + 1), n1 = n0 + 1;
                    uint32_t a0 = mq0[n0 >> 2] >> ((n0 & 3) * 8 + shf);
                    uint32_t a1 = mq1[n0 >> 2] >> ((n0 & 3) * 8 + shf);
                    uint32_t c0 = mq0[n1 >> 2] >> ((n1 & 3) * 8 + shf);
                    uint32_t c1 = mq1[n1 >> 2] >> ((n1 & 3) * 8 + shf);
                    float p0 = (a0 & 1u) ? ex2(sacc[n0][0]) : 0.f;
                    float p1 = (a0 & 2u) ? ex2(sacc[n0][1]) : 0.f;
                    float p2 = (a1 & 1u) ? ex2(sacc[n0][2]) : 0.f;
                    float p3 = (a1 & 2u) ? ex2(sacc[n0][3]) : 0.f;
                    float p4 = (c0 & 1u) ? ex2(sacc[n1][0]) : 0.f;
                    float p5 = (c0 & 2u) ? ex2(sacc[n1][1]) : 0.f;
                    float p6 = (c1 & 1u) ? ex2(sacc[n1][2]) : 0.f;
                    float p7 = (c1 & 2u) ? ex2(sacc[n1][3]) : 0.f;
                    lsum0 += (p0 + p1) + (p4 + p5);
                    lsum1 += (p2 + p3) + (p6 + p7);
                    const int nb = (kt + 1) & 1;
                    AH[nb][0] = packh2(p0, p1); AH[nb][1] = packh2(p2, p3);
                    AH[nb][2] = packh2(p4, p5); AH[nb][3] = packh2(p6, p7);
                }
#pragma unroll
                for (int u = 0; u < 4; u++) {
                    const int j2 = (g & 1) * 4 + u;
                    mma_f16(oacc[2 * j2],     AH[kt & 1], Bb[cur][u]);
                    mma_f16(oacc[2 * j2 + 1], AH[kt & 1], Bb[cur][u] + 2);
                }
            }
        }

        CP_WAIT0();
        __syncthreads();   // next-tile buffers ready; everyone done reading current
    }

    // ---- epilogue: quad-reduce row sums, normalize, store ----
    lsum0 += __shfl_xor_sync(0xffffffffu, lsum0, 1);
    lsum0 += __shfl_xor_sync(0xffffffffu, lsum0, 2);
    lsum1 += __shfl_xor_sync(0xffffffffu, lsum1, 1);
    lsum1 += __shfl_xor_sync(0xffffffffu, lsum1, 2);
    float inv0 = 1.f / lsum0, inv1 = 1.f / lsum1;

    const size_t hbase = (size_t)bh * 262144;
    const int grow0 = qb * 128 + rloc0;
    float* p0 = Out + hbase + (size_t)grow0 * 128 + (lane & 3) * 2;
    float* p1 = p0 + 8 * 128;
#pragma unroll
    for (int dt = 0; dt < 16; dt++) {
        *reinterpret_cast<float2*>(p0 + dt * 8) = make_float2(oacc[dt][0] * inv0, oacc[dt][1] * inv0);
        *reinterpret_cast<float2*>(p1 + dt * 8) = make_float2(oacc[dt][2] * inv1, oacc[dt][3] * inv1);
    }
}

// ---------------------------------------------------------------------------
extern "C" void kernel_launch(void* const* d_in, const int* in_sizes, int n_in,
                              void* d_out, int out_size)
{
    const float* q    = reinterpret_cast<const float*>(d_in[0]);
    const float* k    = reinterpret_cast<const float*>(d_in[1]);
    const float* v    = reinterpret_cast<const float*>(d_in[2]);
    const int*   mask = reinterpret_cast<const int*>(d_in[3]);
    float* out = reinterpret_cast<float*>(d_out);

    cudaFuncSetAttribute(flash_mma_kernel, cudaFuncAttributeMaxDynamicSharedMemorySize, SMEM_B);

    pack_mask_kernel<<<512, 256>>>(mask);
    dim3 pgrid(NELEM / 4 / 256, 3);
    prep_qkv_kernel<<<pgrid, 256>>>(reinterpret_cast<const float4*>(q),
                                    reinterpret_cast<const float4*>(k),
                                    reinterpret_cast<const float4*>(v));

    dim3 grid(16, 64);
    flash_mma_kernel<<<grid, 256, SMEM_B>>>(out);
}

// round 13
// speedup vs baseline: 1.0260x; 1.0260x over previous
#include <cuda_runtime.h>
#include <cuda_fp16.h>
#include <cstdint>

#define NELEM 16777216            // 4*16*2048*128

// ---------------- global scratch (allocation-free) ----------------
__device__ __align__(16) uint32_t g_mask[2048 * 64];
__device__ __align__(16) __half g_qh[NELEM];
__device__ __align__(16) __half g_kh[NELEM];
__device__ __align__(16) __half g_vh[NELEM];

// ---------------- smem: 6-buffer ring (Q uses buf4 then recycled) ----------------
#define ROWH 136
#define BUFB (128 * ROWH * 2)     // 34816 B per 128x128 fp16 tile
#define SMEM_B (6 * BUFB)         // 208896 B

// ---------------- helpers ----------------
__device__ __forceinline__ uint32_t smem_u32(const void* p) {
    uint32_t a;
    asm("{ .reg .u64 t; cvta.to.shared.u64 t, %1; cvt.u32.u64 %0, t; }" : "=r"(a) : "l"(p));
    return a;
}
__device__ __forceinline__ float ex2(float x) {
    float y; asm("ex2.approx.ftz.f32 %0, %1;" : "=f"(y) : "f"(x)); return y;
}
__device__ __forceinline__ uint32_t packh2(float x0, float x1) {
    __half2 h = __floats2half2_rn(x0, x1);
    return *reinterpret_cast<uint32_t*>(&h);
}
__device__ __forceinline__ void mma_f16(float* c, const uint32_t* a, const uint32_t* b) {
    asm volatile("mma.sync.aligned.m16n8k16.row.col.f32.f16.f16.f32 "
        "{%0,%1,%2,%3}, {%4,%5,%6,%7}, {%8,%9}, {%0,%1,%2,%3};"
        : "+f"(c[0]), "+f"(c[1]), "+f"(c[2]), "+f"(c[3])
        : "r"(a[0]), "r"(a[1]), "r"(a[2]), "r"(a[3]), "r"(b[0]), "r"(b[1]));
}
#define LDSM_X4(r, addr) \
    asm volatile("ldmatrix.sync.aligned.m8n8.x4.shared.b16 {%0,%1,%2,%3}, [%4];" \
        : "=r"((r)[0]), "=r"((r)[1]), "=r"((r)[2]), "=r"((r)[3]) : "r"(addr))
#define LDSM_X4T(r, addr) \
    asm volatile("ldmatrix.sync.aligned.m8n8.x4.trans.shared.b16 {%0,%1,%2,%3}, [%4];" \
        : "=r"((r)[0]), "=r"((r)[1]), "=r"((r)[2]), "=r"((r)[3]) : "r"(addr))
__device__ __forceinline__ void cpa16(uint32_t dst, const void* src) {
    asm volatile("cp.async.cg.shared.global [%0], [%1], 16;" :: "r"(dst), "l"(src) : "memory");
}
#define CP_COMMIT() asm volatile("cp.async.commit_group;" ::: "memory")
#define CP_WAIT(n)  asm volatile("cp.async.wait_group %0;" :: "n"(n) : "memory")

// padded byte offset inside a buffer for data uint4 index i (row = i>>4, col16 = i&15)
__device__ __forceinline__ uint32_t pad_off(int i) {
    return (uint32_t)(((i >> 4) * 17 + (i & 15)) * 16);
}

// ---------------- prep kernels (4-launch layout so ncu captures flash) ----------------
__global__ void pack_mask_kernel(const int* __restrict__ mask) {
    int w = blockIdx.x * blockDim.x + threadIdx.x;
    const int4* m4 = reinterpret_cast<const int4*>(mask) + (size_t)w * 8;
    uint32_t b = 0;
#pragma unroll
    for (int i = 0; i < 8; i++) {
        int4 v = m4[i];
        b |= (uint32_t)(v.x != 0) << (i * 4)     | (uint32_t)(v.y != 0) << (i * 4 + 1)
           | (uint32_t)(v.z != 0) << (i * 4 + 2) | (uint32_t)(v.w != 0) << (i * 4 + 3);
    }
    g_mask[w] = b;
}
__global__ void prep_q_kernel(const float4* __restrict__ q) {
    const float CS = 1.4426950408889634f / 11.313708498984761f;  // log2(e)/sqrt(128)
    int i = blockIdx.x * 256 + threadIdx.x;
    float4 x = q[i];
    reinterpret_cast<uint2*>(g_qh)[i] = make_uint2(packh2(x.x * CS, x.y * CS),
                                                   packh2(x.z * CS, x.w * CS));
}
__global__ void prep_kv_kernel(const float4* __restrict__ k, const float4* __restrict__ v) {
    int i = blockIdx.x * 256 + threadIdx.x;
    const float4* src = blockIdx.y ? v : k;
    __half* dst = blockIdx.y ? g_vh : g_kh;
    float4 x = src[i];
    reinterpret_cast<uint2*>(dst)[i] = make_uint2(packh2(x.x, x.y), packh2(x.z, x.w));
}

// ---------------- main kernel: grid(16, 64), 256 threads (8 warps) ----------------
__global__ void __launch_bounds__(256, 1)
flash_mma_kernel(float* __restrict__ Out)
{
    extern __shared__ __align__(16) char smp[];
    const uint32_t sbase = smem_u32(smp);
    const int tid = threadIdx.x, w = tid >> 5, lane = tid & 31;
    const int bh = blockIdx.y, qb = blockIdx.x;

    const size_t TILE4 = 2048;                          // uint4 per 128x128 fp16 tile
    const size_t hbase4 = (size_t)bh * (TILE4 * 16);
    const size_t qtile4 = hbase4 + (size_t)qb * TILE4;

    const uint4* gq4 = reinterpret_cast<const uint4*>(g_qh);
    const uint4* gk4 = reinterpret_cast<const uint4*>(g_kh);
    const uint4* gv4 = reinterpret_cast<const uint4*>(g_vh);

    // ---- prologue: Q -> buf4 ; K0,V0 -> buf0,1 ; K1,V1 -> buf2,3 ----
    for (int i = tid; i < 2048; i += 256)
        cpa16(sbase + 4 * BUFB + pad_off(i), gq4 + qtile4 + i);
    CP_COMMIT();
    for (int i = tid; i < 2048; i += 256) {
        uint32_t po = pad_off(i);
        cpa16(sbase + 0 * BUFB + po, gk4 + hbase4 + i);
        cpa16(sbase + 1 * BUFB + po, gv4 + hbase4 + i);
    }
    CP_COMMIT();
    for (int i = tid; i < 2048; i += 256) {
        uint32_t po = pad_off(i);
        cpa16(sbase + 2 * BUFB + po, gk4 + hbase4 + TILE4 + i);
        cpa16(sbase + 3 * BUFB + po, gv4 + hbase4 + TILE4 + i);
    }
    CP_COMMIT();

    float sacc[16][4], oacc[16][4];
    float lsum0 = 0.f, lsum1 = 0.f;
#pragma unroll
    for (int i = 0; i < 16; i++) {
        oacc[i][0] = oacc[i][1] = oacc[i][2] = oacc[i][3] = 0.f;
        sacc[i][0] = sacc[i][1] = sacc[i][2] = sacc[i][3] = 0.f;
    }

    // per-thread ldmatrix base byte addresses (mapping validated R7-R12)
    const uint32_t aQ  = sbase + 4 * BUFB + (w * 16 + (lane & 15)) * 272 + ((lane & 16) ? 16 : 0);
    const uint32_t bK  = ((lane >> 4) * 8 + (lane & 7)) * 272 + ((lane & 8) ? 16 : 0);
    const uint32_t vVb = (lane & 15) * 272 + ((lane >> 4) ? 16 : 0);

    const int rloc0 = w * 16 + (lane >> 2);
    const int shf = (lane & 3) * 2;
    const uint32_t* mrow0 = g_mask + (size_t)(qb * 128 + rloc0) * 64;
    const uint32_t* mrow1 = mrow0 + 8 * 64;

    CP_WAIT(1);            // Q + K0/V0 arrived
    __syncthreads();

    // ---- hoist Q fragments to registers (buf4 freed for ring after this) ----
    uint32_t Qf[8][4];
#pragma unroll
    for (int kt = 0; kt < 8; kt++) LDSM_X4(Qf[kt], aQ + kt * 32);

    // ---- S(0) standalone ----
#pragma unroll
    for (int it = 0; it < 64; it++) {
        const int kt = it >> 3, j2 = it & 7;
        uint32_t B4[4];
        LDSM_X4(B4, sbase + 0 * BUFB + bK + j2 * 4352 + kt * 32);
        mma_f16(sacc[2 * j2],     Qf[kt], B4);
        mma_f16(sacc[2 * j2 + 1], Qf[kt], B4 + 2);
    }

    uint32_t AH[8][4];

#pragma unroll 1
    for (int t = 0; t < 16; t++) {
        // ---- convert P(t): mask + exp2 + pack ; zero sacc for S(t+1) ----
        uint32_t mq0[4], mq1[4];
#pragma unroll
        for (int d_ = 0; d_ < 4; d_++) {
            mq0[d_] = __ldg(mrow0 + t * 4 + d_);
            mq1[d_] = __ldg(mrow1 + t * 4 + d_);
        }
#pragma unroll
        for (int kt = 0; kt < 8; kt++) {
            const int n0 = 2 * kt, n1 = 2 * kt + 1;
            uint32_t a0 = mq0[n0 >> 2] >> ((n0 & 3) * 8 + shf);
            uint32_t a1 = mq1[n0 >> 2] >> ((n0 & 3) * 8 + shf);
            uint32_t c0 = mq0[n1 >> 2] >> ((n1 & 3) * 8 + shf);
            uint32_t c1 = mq1[n1 >> 2] >> ((n1 & 3) * 8 + shf);
            float p0 = (a0 & 1u) ? ex2(sacc[n0][0]) : 0.f;
            float p1 = (a0 & 2u) ? ex2(sacc[n0][1]) : 0.f;
            float p2 = (a1 & 1u) ? ex2(sacc[n0][2]) : 0.f;
            float p3 = (a1 & 2u) ? ex2(sacc[n0][3]) : 0.f;
            float p4 = (c0 & 1u) ? ex2(sacc[n1][0]) : 0.f;
            float p5 = (c0 & 2u) ? ex2(sacc[n1][1]) : 0.f;
            float p6 = (c1 & 1u) ? ex2(sacc[n1][2]) : 0.f;
            float p7 = (c1 & 2u) ? ex2(sacc[n1][3]) : 0.f;
            lsum0 += (p0 + p1) + (p4 + p5);
            lsum1 += (p2 + p3) + (p6 + p7);
            AH[kt][0] = packh2(p0, p1);
            AH[kt][1] = packh2(p2, p3);
            AH[kt][2] = packh2(p4, p5);
            AH[kt][3] = packh2(p6, p7);
            sacc[n0][0] = sacc[n0][1] = sacc[n0][2] = sacc[n0][3] = 0.f;
            sacc[n1][0] = sacc[n1][1] = sacc[n1][2] = sacc[n1][3] = 0.f;
        }

        CP_WAIT(0);          // K/V(t+1) arrived (sole outstanding group)
        __syncthreads();     // visibility + read-safety for ring reuse

        if (t + 2 <= 15) {   // prefetch K/V(t+2) into buffers freed at this barrier
            const uint32_t kb = sbase + (uint32_t)((2 * t + 4) % 6) * BUFB;
            const uint32_t vb = sbase + (uint32_t)((2 * t + 5) % 6) * BUFB;
            const size_t toff = hbase4 + (size_t)(t + 2) * TILE4;
            for (int i = tid; i < 2048; i += 256) {
                uint32_t po = pad_off(i);
                cpa16(kb + po, gk4 + toff + i);
                cpa16(vb + po, gv4 + toff + i);
            }
            CP_COMMIT();
        }

        const uint32_t vcur = sbase + (uint32_t)((2 * t + 1) % 6) * BUFB;
        if (t < 15) {
            // ---- fused: S(t+1) + PV(t) — two independent chains per warp ----
            const uint32_t knxt = sbase + (uint32_t)((2 * t + 2) % 6) * BUFB;
#pragma unroll
            for (int it = 0; it < 64; it++) {
                const int kt = it >> 3, j2 = it & 7;
                uint32_t Bk[4], Bv[4];
                LDSM_X4 (Bk, knxt + bK  + j2 * 4352 + kt * 32);
                LDSM_X4T(Bv, vcur + vVb + kt * 4352 + j2 * 32);
                mma_f16(sacc[2 * j2],     Qf[kt], Bk);
                mma_f16(sacc[2 * j2 + 1], Qf[kt], Bk + 2);
                mma_f16(oacc[2 * j2],     AH[kt], Bv);
                mma_f16(oacc[2 * j2 + 1], AH[kt], Bv + 2);
            }
        } else {
            // ---- last tile: PV(15) only ----
#pragma unroll
            for (int it = 0; it < 64; it++) {
                const int kt = it >> 3, j2 = it & 7;
                uint32_t Bv[4];
                LDSM_X4T(Bv, vcur + vVb + kt * 4352 + j2 * 32);
                mma_f16(oacc[2 * j2],     AH[kt], Bv);
                mma_f16(oacc[2 * j2 + 1], AH[kt], Bv + 2);
            }
        }
    }

    // ---- epilogue: quad-reduce row sums, normalize, store ----
    lsum0 += __shfl_xor_sync(0xffffffffu, lsum0, 1);
    lsum0 += __shfl_xor_sync(0xffffffffu, lsum0, 2);
    lsum1 += __shfl_xor_sync(0xffffffffu, lsum1, 1);
    lsum1 += __shfl_xor_sync(0xffffffffu, lsum1, 2);
    float inv0 = 1.f / lsum0, inv1 = 1.f / lsum1;

    const size_t hbase = (size_t)bh * 262144;
    const int grow0 = qb * 128 + rloc0;
    float* p0 = Out + hbase + (size_t)grow0 * 128 + (lane & 3) * 2;
    float* p1 = p0 + 8 * 128;
#pragma unroll
    for (int dt = 0; dt < 16; dt++) {
        *reinterpret_cast<float2*>(p0 + dt * 8) = make_float2(oacc[dt][0] * inv0, oacc[dt][1] * inv0);
        *reinterpret_cast<float2*>(p1 + dt * 8) = make_float2(oacc[dt][2] * inv1, oacc[dt][3] * inv1);
    }
}

// ---------------------------------------------------------------------------
extern "C" void kernel_launch(void* const* d_in, const int* in_sizes, int n_in,
                              void* d_out, int out_size)
{
    const float* q    = reinterpret_cast<const float*>(d_in[0]);
    const float* k    = reinterpret_cast<const float*>(d_in[1]);
    const float* v    = reinterpret_cast<const float*>(d_in[2]);
    const int*   mask = reinterpret_cast<const int*>(d_in[3]);
    float* out = reinterpret_cast<float*>(d_out);

    cudaFuncSetAttribute(flash_mma_kernel, cudaFuncAttributeMaxDynamicSharedMemorySize, SMEM_B);

    pack_mask_kernel<<<512, 256>>>(mask);
    prep_q_kernel<<<NELEM / 4 / 256, 256>>>(reinterpret_cast<const float4*>(q));
    dim3 kvgrid(NELEM / 4 / 256, 2);
    prep_kv_kernel<<<kvgrid, 256>>>(reinterpret_cast<const float4*>(k),
                                    reinterpret_cast<const float4*>(v));

    dim3 grid(16, 64);
    flash_mma_kernel<<<grid, 256, SMEM_B>>>(out);
}

// round 14
// speedup vs baseline: 1.0438x; 1.0174x over previous
#include <cuda_runtime.h>
#include <cuda_fp16.h>
#include <cstdint>

#define NELEM 16777216            // 4*16*2048*128

// ---------------- global scratch (allocation-free) ----------------
__device__ __align__(16) uint32_t g_mask[2048 * 64];
__device__ __align__(16) __half g_qh[NELEM];
__device__ __align__(16) __half g_kh[NELEM];
__device__ __align__(16) __half g_vh[NELEM];

// ---------------- smem: 6-buffer ring of 64x128 fp16 tiles ----------------
#define ROWH 136
#define BUFB (64 * ROWH * 2)      // 17408 B per 64x128 fp16 tile
#define SMEM_B (6 * BUFB)         // 104448 B -> 2 CTAs/SM

// ---------------- helpers ----------------
__device__ __forceinline__ uint32_t smem_u32(const void* p) {
    uint32_t a;
    asm("{ .reg .u64 t; cvta.to.shared.u64 t, %1; cvt.u32.u64 %0, t; }" : "=r"(a) : "l"(p));
    return a;
}
__device__ __forceinline__ float ex2(float x) {
    float y; asm("ex2.approx.ftz.f32 %0, %1;" : "=f"(y) : "f"(x)); return y;
}
__device__ __forceinline__ uint32_t packh2(float x0, float x1) {
    __half2 h = __floats2half2_rn(x0, x1);
    return *reinterpret_cast<uint32_t*>(&h);
}
__device__ __forceinline__ void mma_f16(float* c, const uint32_t* a, const uint32_t* b) {
    asm volatile("mma.sync.aligned.m16n8k16.row.col.f32.f16.f16.f32 "
        "{%0,%1,%2,%3}, {%4,%5,%6,%7}, {%8,%9}, {%0,%1,%2,%3};"
        : "+f"(c[0]), "+f"(c[1]), "+f"(c[2]), "+f"(c[3])
        : "r"(a[0]), "r"(a[1]), "r"(a[2]), "r"(a[3]), "r"(b[0]), "r"(b[1]));
}
#define LDSM_X4(r, addr) \
    asm volatile("ldmatrix.sync.aligned.m8n8.x4.shared.b16 {%0,%1,%2,%3}, [%4];" \
        : "=r"((r)[0]), "=r"((r)[1]), "=r"((r)[2]), "=r"((r)[3]) : "r"(addr))
#define LDSM_X4T(r, addr) \
    asm volatile("ldmatrix.sync.aligned.m8n8.x4.trans.shared.b16 {%0,%1,%2,%3}, [%4];" \
        : "=r"((r)[0]), "=r"((r)[1]), "=r"((r)[2]), "=r"((r)[3]) : "r"(addr))
__device__ __forceinline__ void cpa16(uint32_t dst, const void* src) {
    asm volatile("cp.async.cg.shared.global [%0], [%1], 16;" :: "r"(dst), "l"(src) : "memory");
}
#define CP_COMMIT() asm volatile("cp.async.commit_group;" ::: "memory")
#define CP_WAIT(n)  asm volatile("cp.async.wait_group %0;" :: "n"(n) : "memory")

// padded byte offset inside a buffer for data uint4 index i (row = i>>4, col16 = i&15)
__device__ __forceinline__ uint32_t pad_off(int i) {
    return (uint32_t)(((i >> 4) * 17 + (i & 15)) * 16);
}

// ---------------- prep kernels ----------------
__global__ void pack_mask_kernel(const int* __restrict__ mask) {
    int w = blockIdx.x * blockDim.x + threadIdx.x;
    const int4* m4 = reinterpret_cast<const int4*>(mask) + (size_t)w * 8;
    uint32_t b = 0;
#pragma unroll
    for (int i = 0; i < 8; i++) {
        int4 v = m4[i];
        b |= (uint32_t)(v.x != 0) << (i * 4)     | (uint32_t)(v.y != 0) << (i * 4 + 1)
           | (uint32_t)(v.z != 0) << (i * 4 + 2) | (uint32_t)(v.w != 0) << (i * 4 + 3);
    }
    g_mask[w] = b;
}
__global__ void prep_q_kernel(const float4* __restrict__ q) {
    const float CS = 1.4426950408889634f / 11.313708498984761f;  // log2(e)/sqrt(128)
    int i = blockIdx.x * 256 + threadIdx.x;
    float4 x = q[i];
    reinterpret_cast<uint2*>(g_qh)[i] = make_uint2(packh2(x.x * CS, x.y * CS),
                                                   packh2(x.z * CS, x.w * CS));
}
__global__ void prep_kv_kernel(const float4* __restrict__ k, const float4* __restrict__ v) {
    int i = blockIdx.x * 256 + threadIdx.x;
    const float4* src = blockIdx.y ? v : k;
    __half* dst = blockIdx.y ? g_vh : g_kh;
    float4 x = src[i];
    reinterpret_cast<uint2*>(dst)[i] = make_uint2(packh2(x.x, x.y), packh2(x.z, x.w));
}

// ---------------- main kernel: grid(32, 64), 128 threads (4 warps), 2 CTAs/SM ----
__global__ void __launch_bounds__(128, 2)
flash_mma_kernel(float* __restrict__ Out)
{
    extern __shared__ __align__(16) char smp[];
    const uint32_t sbase = smem_u32(smp);
    const int tid = threadIdx.x, w = tid >> 5, lane = tid & 31;
    const int bh = blockIdx.y, qb = blockIdx.x;

    const size_t TILE4 = 1024;                          // uint4 per 64x128 fp16 tile
    const size_t hbase4 = (size_t)bh * (TILE4 * 32);    // 32 k-tiles per head
    const size_t qtile4 = hbase4 + (size_t)qb * TILE4;  // CTA's 64 Q rows

    const uint4* gq4 = reinterpret_cast<const uint4*>(g_qh);
    const uint4* gk4 = reinterpret_cast<const uint4*>(g_kh);
    const uint4* gv4 = reinterpret_cast<const uint4*>(g_vh);

    // ---- prologue: Q -> buf4 ; K0,V0 -> buf0,1 ; K1,V1 -> buf2,3 ----
    for (int i = tid; i < 1024; i += 128)
        cpa16(sbase + 4 * BUFB + pad_off(i), gq4 + qtile4 + i);
    CP_COMMIT();
    for (int i = tid; i < 1024; i += 128) {
        uint32_t po = pad_off(i);
        cpa16(sbase + 0 * BUFB + po, gk4 + hbase4 + i);
        cpa16(sbase + 1 * BUFB + po, gv4 + hbase4 + i);
    }
    CP_COMMIT();
    for (int i = tid; i < 1024; i += 128) {
        uint32_t po = pad_off(i);
        cpa16(sbase + 2 * BUFB + po, gk4 + hbase4 + TILE4 + i);
        cpa16(sbase + 3 * BUFB + po, gv4 + hbase4 + TILE4 + i);
    }
    CP_COMMIT();

    float sacc[8][4], oacc[16][4];
    float lsum0 = 0.f, lsum1 = 0.f;
#pragma unroll
    for (int i = 0; i < 16; i++) { oacc[i][0] = oacc[i][1] = oacc[i][2] = oacc[i][3] = 0.f; }
#pragma unroll
    for (int i = 0; i < 8; i++)  { sacc[i][0] = sacc[i][1] = sacc[i][2] = sacc[i][3] = 0.f; }

    // per-thread ldmatrix base byte addresses (same lane mapping as R7-R13)
    const uint32_t aQ  = sbase + 4 * BUFB + (w * 16 + (lane & 15)) * 272 + ((lane & 16) ? 16 : 0);
    const uint32_t bK  = ((lane >> 4) * 8 + (lane & 7)) * 272 + ((lane & 8) ? 16 : 0);
    const uint32_t vVb = (lane & 15) * 272 + ((lane >> 4) ? 16 : 0);

    const int rloc0 = w * 16 + (lane >> 2);             // 0..63
    const int shf = (lane & 3) * 2;
    const uint32_t* mrow0 = g_mask + (size_t)(qb * 64 + rloc0) * 64;
    const uint32_t* mrow1 = mrow0 + 8 * 64;

    CP_WAIT(1);            // Q + K0/V0 arrived
    __syncthreads();

    // ---- hoist Q fragments to registers (buf4 freed for ring after this) ----
    uint32_t Qf[8][4];
#pragma unroll
    for (int kt = 0; kt < 8; kt++) LDSM_X4(Qf[kt], aQ + kt * 32);

    // ---- S(0) standalone: M=64 x N=64 x K=128 ----
#pragma unroll
    for (int it = 0; it < 32; it++) {
        const int kS = it >> 2, jS = it & 3;
        uint32_t B4[4];
        LDSM_X4(B4, sbase + 0 * BUFB + bK + jS * 4352 + kS * 32);
        mma_f16(sacc[2 * jS],     Qf[kS], B4);
        mma_f16(sacc[2 * jS + 1], Qf[kS], B4 + 2);
    }

    uint32_t AH[4][4];

#pragma unroll 1
    for (int t = 0; t < 32; t++) {
        // ---- convert P(t): mask + exp2 + pack ; zero sacc for S(t+1) ----
        uint32_t mq0[2], mq1[2];
        mq0[0] = __ldg(mrow0 + t * 2);     mq0[1] = __ldg(mrow0 + t * 2 + 1);
        mq1[0] = __ldg(mrow1 + t * 2);     mq1[1] = __ldg(mrow1 + t * 2 + 1);
#pragma unroll
        for (int kt = 0; kt < 4; kt++) {
            const int n0 = 2 * kt, n1 = 2 * kt + 1;
            uint32_t a0 = mq0[n0 >> 2] >> ((n0 & 3) * 8 + shf);
            uint32_t a1 = mq1[n0 >> 2] >> ((n0 & 3) * 8 + shf);
            uint32_t c0 = mq0[n1 >> 2] >> ((n1 & 3) * 8 + shf);
            uint32_t c1 = mq1[n1 >> 2] >> ((n1 & 3) * 8 + shf);
            float p0 = (a0 & 1u) ? ex2(sacc[n0][0]) : 0.f;
            float p1 = (a0 & 2u) ? ex2(sacc[n0][1]) : 0.f;
            float p2 = (a1 & 1u) ? ex2(sacc[n0][2]) : 0.f;
            float p3 = (a1 & 2u) ? ex2(sacc[n0][3]) : 0.f;
            float p4 = (c0 & 1u) ? ex2(sacc[n1][0]) : 0.f;
            float p5 = (c0 & 2u) ? ex2(sacc[n1][1]) : 0.f;
            float p6 = (c1 & 1u) ? ex2(sacc[n1][2]) : 0.f;
            float p7 = (c1 & 2u) ? ex2(sacc[n1][3]) : 0.f;
            lsum0 += (p0 + p1) + (p4 + p5);
            lsum1 += (p2 + p3) + (p6 + p7);
            AH[kt][0] = packh2(p0, p1);
            AH[kt][1] = packh2(p2, p3);
            AH[kt][2] = packh2(p4, p5);
            AH[kt][3] = packh2(p6, p7);
            sacc[n0][0] = sacc[n0][1] = sacc[n0][2] = sacc[n0][3] = 0.f;
            sacc[n1][0] = sacc[n1][1] = sacc[n1][2] = sacc[n1][3] = 0.f;
        }

        CP_WAIT(0);          // K/V(t+1) arrived (sole outstanding group)
        __syncthreads();     // visibility + read-safety for ring reuse

        if (t + 2 <= 31) {   // prefetch K/V(t+2) into buffers freed at this barrier
            const uint32_t kb = sbase + (uint32_t)((2 * t + 4) % 6) * BUFB;
            const uint32_t vb = sbase + (uint32_t)((2 * t + 5) % 6) * BUFB;
            const size_t toff = hbase4 + (size_t)(t + 2) * TILE4;
            for (int i = tid; i < 1024; i += 128) {
                uint32_t po = pad_off(i);
                cpa16(kb + po, gk4 + toff + i);
                cpa16(vb + po, gv4 + toff + i);
            }
            CP_COMMIT();
        }

        const uint32_t vcur = sbase + (uint32_t)((2 * t + 1) % 6) * BUFB;
        if (t < 31) {
            // ---- fused: S(t+1) + PV(t) — two independent chains per warp ----
            const uint32_t knxt = sbase + (uint32_t)((2 * t + 2) % 6) * BUFB;
#pragma unroll
            for (int it = 0; it < 32; it++) {
                const int kS = it >> 2, jS = it & 3;    // S: d-chunk, n-tile pair
                const int kV = it >> 3, jV = it & 7;    // PV: kv-chunk, d-tile pair
                uint32_t Bk[4], Bv[4];
                LDSM_X4 (Bk, knxt + bK  + jS * 4352 + kS * 32);
                LDSM_X4T(Bv, vcur + vVb + kV * 4352 + jV * 32);
                mma_f16(sacc[2 * jS],     Qf[kS], Bk);
                mma_f16(sacc[2 * jS + 1], Qf[kS], Bk + 2);
                mma_f16(oacc[2 * jV],     AH[kV], Bv);
                mma_f16(oacc[2 * jV + 1], AH[kV], Bv + 2);
            }
        } else {
            // ---- last tile: PV(31) only ----
#pragma unroll
            for (int it = 0; it < 32; it++) {
                const int kV = it >> 3, jV = it & 7;
                uint32_t Bv[4];
                LDSM_X4T(Bv, vcur + vVb + kV * 4352 + jV * 32);
                mma_f16(oacc[2 * jV],     AH[kV], Bv);
                mma_f16(oacc[2 * jV + 1], AH[kV], Bv + 2);
            }
        }
    }

    // ---- epilogue: quad-reduce row sums, normalize, store ----
    lsum0 += __shfl_xor_sync(0xffffffffu, lsum0, 1);
    lsum0 += __shfl_xor_sync(0xffffffffu, lsum0, 2);
    lsum1 += __shfl_xor_sync(0xffffffffu, lsum1, 1);
    lsum1 += __shfl_xor_sync(0xffffffffu, lsum1, 2);
    float inv0 = 1.f / lsum0, inv1 = 1.f / lsum1;

    const size_t hbase = (size_t)bh * 262144;
    const int grow0 = qb * 64 + rloc0;
    float* p0 = Out + hbase + (size_t)grow0 * 128 + (lane & 3) * 2;
    float* p1 = p0 + 8 * 128;
#pragma unroll
    for (int dt = 0; dt < 16; dt++) {
        *reinterpret_cast<float2*>(p0 + dt * 8) = make_float2(oacc[dt][0] * inv0, oacc[dt][1] * inv0);
        *reinterpret_cast<float2*>(p1 + dt * 8) = make_float2(oacc[dt][2] * inv1, oacc[dt][3] * inv1);
    }
}

// ---------------------------------------------------------------------------
extern "C" void kernel_launch(void* const* d_in, const int* in_sizes, int n_in,
                              void* d_out, int out_size)
{
    const float* q    = reinterpret_cast<const float*>(d_in[0]);
    const float* k    = reinterpret_cast<const float*>(d_in[1]);
    const float* v    = reinterpret_cast<const float*>(d_in[2]);
    const int*   mask = reinterpret_cast<const int*>(d_in[3]);
    float* out = reinterpret_cast<float*>(d_out);

    cudaFuncSetAttribute(flash_mma_kernel, cudaFuncAttributeMaxDynamicSharedMemorySize, SMEM_B);

    pack_mask_kernel<<<512, 256>>>(mask);
    prep_q_kernel<<<NELEM / 4 / 256, 256>>>(reinterpret_cast<const float4*>(q));
    dim3 kvgrid(NELEM / 4 / 256, 2);
    prep_kv_kernel<<<kvgrid, 256>>>(reinterpret_cast<const float4*>(k),
                                    reinterpret_cast<const float4*>(v));

    dim3 grid(32, 64);
    flash_mma_kernel<<<grid, 128, SMEM_B>>>(out);
}

// round 15
// speedup vs baseline: 1.1335x; 1.0859x over previous
#include <cuda_runtime.h>
#include <cuda_fp16.h>
#include <cstdint>

#define NELEM 16777216            // 4*16*2048*128

// ---------------- global scratch (allocation-free) ----------------
__device__ __align__(16) uint32_t g_mask[2048 * 64];
__device__ __align__(16) __half g_qh[NELEM];
__device__ __align__(16) __half g_kh[NELEM];
__device__ __align__(16) __half g_vh[NELEM];

// ---------------- smem: persistent Q (128 rows) + 4-buffer K/V ring (64-row tiles)
#define ROWB 272                  // padded row stride in bytes (136 halves)
#define QBUF_B (128 * ROWB)       // 34816
#define KVB    (64 * ROWB)        // 17408 per 64x128 tile
#define SMEM_B (QBUF_B + 4 * KVB) // 104448 -> 2 CTAs/SM

// ---------------- helpers ----------------
__device__ __forceinline__ uint32_t smem_u32(const void* p) {
    uint32_t a;
    asm("{ .reg .u64 t; cvta.to.shared.u64 t, %1; cvt.u32.u64 %0, t; }" : "=r"(a) : "l"(p));
    return a;
}
__device__ __forceinline__ float ex2(float x) {
    float y; asm("ex2.approx.ftz.f32 %0, %1;" : "=f"(y) : "f"(x)); return y;
}
__device__ __forceinline__ uint32_t packh2(float x0, float x1) {
    __half2 h = __floats2half2_rn(x0, x1);
    return *reinterpret_cast<uint32_t*>(&h);
}
__device__ __forceinline__ void mma_f16(float* c, const uint32_t* a, const uint32_t* b) {
    asm volatile("mma.sync.aligned.m16n8k16.row.col.f32.f16.f16.f32 "
        "{%0,%1,%2,%3}, {%4,%5,%6,%7}, {%8,%9}, {%0,%1,%2,%3};"
        : "+f"(c[0]), "+f"(c[1]), "+f"(c[2]), "+f"(c[3])
        : "r"(a[0]), "r"(a[1]), "r"(a[2]), "r"(a[3]), "r"(b[0]), "r"(b[1]));
}
#define LDSM_X4(r, addr) \
    asm volatile("ldmatrix.sync.aligned.m8n8.x4.shared.b16 {%0,%1,%2,%3}, [%4];" \
        : "=r"((r)[0]), "=r"((r)[1]), "=r"((r)[2]), "=r"((r)[3]) : "r"(addr))
#define LDSM_X4T(r, addr) \
    asm volatile("ldmatrix.sync.aligned.m8n8.x4.trans.shared.b16 {%0,%1,%2,%3}, [%4];" \
        : "=r"((r)[0]), "=r"((r)[1]), "=r"((r)[2]), "=r"((r)[3]) : "r"(addr))
__device__ __forceinline__ void cpa16(uint32_t dst, const void* src) {
    asm volatile("cp.async.cg.shared.global [%0], [%1], 16;" :: "r"(dst), "l"(src) : "memory");
}
#define CP_COMMIT() asm volatile("cp.async.commit_group;" ::: "memory")
#define CP_WAIT(n)  asm volatile("cp.async.wait_group %0;" :: "n"(n) : "memory")

// padded byte offset for data uint4 index i (row = i>>4, col16 = i&15)
__device__ __forceinline__ uint32_t pad_off(int i) {
    return (uint32_t)(((i >> 4) * 17 + (i & 15)) * 16);
}

// ---------------- prep kernels ----------------
__global__ void pack_mask_kernel(const int* __restrict__ mask) {
    int w = blockIdx.x * blockDim.x + threadIdx.x;
    const int4* m4 = reinterpret_cast<const int4*>(mask) + (size_t)w * 8;
    uint32_t b = 0;
#pragma unroll
    for (int i = 0; i < 8; i++) {
        int4 v = m4[i];
        b |= (uint32_t)(v.x != 0) << (i * 4)     | (uint32_t)(v.y != 0) << (i * 4 + 1)
           | (uint32_t)(v.z != 0) << (i * 4 + 2) | (uint32_t)(v.w != 0) << (i * 4 + 3);
    }
    g_mask[w] = b;
}
__global__ void prep_q_kernel(const float4* __restrict__ q) {
    const float CS = 1.4426950408889634f / 11.313708498984761f;  // log2(e)/sqrt(128)
    int i = blockIdx.x * 256 + threadIdx.x;
    float4 x = q[i];
    reinterpret_cast<uint2*>(g_qh)[i] = make_uint2(packh2(x.x * CS, x.y * CS),
                                                   packh2(x.z * CS, x.w * CS));
}
__global__ void prep_kv_kernel(const float4* __restrict__ k, const float4* __restrict__ v) {
    int i = blockIdx.x * 256 + threadIdx.x;
    const float4* src = blockIdx.y ? v : k;
    __half* dst = blockIdx.y ? g_vh : g_kh;
    float4 x = src[i];
    reinterpret_cast<uint2*>(dst)[i] = make_uint2(packh2(x.x, x.y), packh2(x.z, x.w));
}

// ---------------- main kernel: grid(16, 64), 128 threads (4 warps x 32 rows) ------
__global__ void __launch_bounds__(128, 2)
flash_mma_kernel(float* __restrict__ Out)
{
    extern __shared__ __align__(16) char smp[];
    const uint32_t sbase = smem_u32(smp);
    const int tid = threadIdx.x, w = tid >> 5, lane = tid & 31;
    const int bh = blockIdx.y, qb = blockIdx.x;

    const size_t KV4 = 1024;                            // uint4 per 64x128 fp16 tile
    const size_t hbase4 = (size_t)bh * (KV4 * 32);      // 32 k-tiles per head
    const size_t qtile4 = (size_t)bh * 32768 + (size_t)qb * 2048;  // 128 Q rows = 2048 uint4

    const uint4* gq4 = reinterpret_cast<const uint4*>(g_qh);
    const uint4* gk4 = reinterpret_cast<const uint4*>(g_kh);
    const uint4* gv4 = reinterpret_cast<const uint4*>(g_vh);

    // ---- prologue: G0 = {Q, K0, V0} ; G1 = {K1, V1} ----
    for (int i = tid; i < 2048; i += 128)
        cpa16(sbase + pad_off(i), gq4 + qtile4 + i);
    for (int i = tid; i < 1024; i += 128) {
        uint32_t po = pad_off(i);
        cpa16(sbase + QBUF_B + 0 * KVB + po, gk4 + hbase4 + i);
        cpa16(sbase + QBUF_B + 1 * KVB + po, gv4 + hbase4 + i);
    }
    CP_COMMIT();
    for (int i = tid; i < 1024; i += 128) {
        uint32_t po = pad_off(i);
        cpa16(sbase + QBUF_B + 2 * KVB + po, gk4 + hbase4 + KV4 + i);
        cpa16(sbase + QBUF_B + 3 * KVB + po, gv4 + hbase4 + KV4 + i);
    }
    CP_COMMIT();

    float oacc[2][16][4];
    float lsum0[2], lsum1[2];
#pragma unroll
    for (int mt = 0; mt < 2; mt++) {
        lsum0[mt] = lsum1[mt] = 0.f;
#pragma unroll
        for (int i = 0; i < 16; i++)
            oacc[mt][i][0] = oacc[mt][i][1] = oacc[mt][i][2] = oacc[mt][i][3] = 0.f;
    }

    // per-thread ldmatrix base byte addresses
    // Q A-frag (mt, kt): rows 32w+16mt+(lane&15), halves col 16kt + 8*(lane>>4)
    const uint32_t aQ0 = sbase + (w * 32 + (lane & 15)) * ROWB + ((lane & 16) ? 16 : 0);
    const uint32_t bK  = ((lane >> 4) * 8 + (lane & 7)) * ROWB + ((lane & 8) ? 16 : 0);
    const uint32_t vVb = (lane & 15) * ROWB + ((lane >> 4) ? 16 : 0);

    const int shf = (lane & 3) * 2;
    const int r0 = w * 32 + (lane >> 2);                // mt=0 base row (local)
    const uint32_t* mbase = g_mask + (size_t)(qb * 128) * 64;

#pragma unroll 1
    for (int t = 0; t < 32; t++) {
        if (t == 31) { CP_WAIT(0); } else { CP_WAIT(1); }
        __syncthreads();    // K(t)/V(t) visible to all warps

        const uint32_t kcur = sbase + QBUF_B + (uint32_t)(2 * (t & 1)) * KVB;
        const uint32_t vcur = kcur + KVB;

        // ---- S-phase: S[32 x 64] per warp, Q A-frags reloaded from smem ----
        float sacc[2][8][4];
#pragma unroll
        for (int mt = 0; mt < 2; mt++)
#pragma unroll
            for (int j = 0; j < 8; j++)
                sacc[mt][j][0] = sacc[mt][j][1] = sacc[mt][j][2] = sacc[mt][j][3] = 0.f;
#pragma unroll
        for (int kt = 0; kt < 8; kt++) {
            uint32_t Qa[2][4];
            LDSM_X4(Qa[0], aQ0 + kt * 32);
            LDSM_X4(Qa[1], aQ0 + 16 * ROWB + kt * 32);
#pragma unroll
            for (int jS = 0; jS < 4; jS++) {
                uint32_t Bk[4];
                LDSM_X4(Bk, kcur + bK + jS * (16 * ROWB) + kt * 32);
                mma_f16(sacc[0][2 * jS],     Qa[0], Bk);
                mma_f16(sacc[0][2 * jS + 1], Qa[0], Bk + 2);
                mma_f16(sacc[1][2 * jS],     Qa[1], Bk);
                mma_f16(sacc[1][2 * jS + 1], Qa[1], Bk + 2);
            }
        }

        // ---- convert: mask + exp2 + pack to A-frags ----
        uint32_t AH[2][4][4];
#pragma unroll
        for (int mt = 0; mt < 2; mt++) {
            const int ra = r0 + 16 * mt;
            uint32_t mq0[2], mq1[2];
            mq0[0] = __ldg(mbase + (size_t)ra * 64 + t * 2);
            mq0[1] = __ldg(mbase + (size_t)ra * 64 + t * 2 + 1);
            mq1[0] = __ldg(mbase + (size_t)(ra + 8) * 64 + t * 2);
            mq1[1] = __ldg(mbase + (size_t)(ra + 8) * 64 + t * 2 + 1);
#pragma unroll
            for (int kt = 0; kt < 4; kt++) {
                const int n0 = 2 * kt, n1 = 2 * kt + 1;
                uint32_t a0 = mq0[n0 >> 2] >> ((n0 & 3) * 8 + shf);
                uint32_t a1 = mq1[n0 >> 2] >> ((n0 & 3) * 8 + shf);
                uint32_t c0 = mq0[n1 >> 2] >> ((n1 & 3) * 8 + shf);
                uint32_t c1 = mq1[n1 >> 2] >> ((n1 & 3) * 8 + shf);
                float p0 = (a0 & 1u) ? ex2(sacc[mt][n0][0]) : 0.f;
                float p1 = (a0 & 2u) ? ex2(sacc[mt][n0][1]) : 0.f;
                float p2 = (a1 & 1u) ? ex2(sacc[mt][n0][2]) : 0.f;
                float p3 = (a1 & 2u) ? ex2(sacc[mt][n0][3]) : 0.f;
                float p4 = (c0 & 1u) ? ex2(sacc[mt][n1][0]) : 0.f;
                float p5 = (c0 & 2u) ? ex2(sacc[mt][n1][1]) : 0.f;
                float p6 = (c1 & 1u) ? ex2(sacc[mt][n1][2]) : 0.f;
                float p7 = (c1 & 2u) ? ex2(sacc[mt][n1][3]) : 0.f;
                lsum0[mt] += (p0 + p1) + (p4 + p5);
                lsum1[mt] += (p2 + p3) + (p6 + p7);
                AH[mt][kt][0] = packh2(p0, p1);
                AH[mt][kt][1] = packh2(p2, p3);
                AH[mt][kt][2] = packh2(p4, p5);
                AH[mt][kt][3] = packh2(p6, p7);
            }
        }

        // ---- PV-phase: O += P V ----
#pragma unroll
        for (int kt = 0; kt < 4; kt++) {
#pragma unroll
            for (int jV = 0; jV < 8; jV++) {
                uint32_t Bv[4];
                LDSM_X4T(Bv, vcur + vVb + kt * (16 * ROWB) + jV * 32);
                mma_f16(oacc[0][2 * jV],     AH[0][kt], Bv);
                mma_f16(oacc[0][2 * jV + 1], AH[0][kt], Bv + 2);
                mma_f16(oacc[1][2 * jV],     AH[1][kt], Bv);
                mma_f16(oacc[1][2 * jV + 1], AH[1][kt], Bv + 2);
            }
        }

        __syncthreads();    // all warps done reading K(t)/V(t) before ring reuse
        if (t + 2 < 32) {   // prefetch K/V(t+2) into the buffers just freed
            const size_t toff = hbase4 + (size_t)(t + 2) * KV4;
            for (int i = tid; i < 1024; i += 128) {
                uint32_t po = pad_off(i);
                cpa16(kcur + po, gk4 + toff + i);
                cpa16(vcur + po, gv4 + toff + i);
            }
            CP_COMMIT();
        }
    }

    // ---- epilogue: quad-reduce row sums, normalize, store ----
    const size_t hbase = (size_t)bh * 262144;
#pragma unroll
    for (int mt = 0; mt < 2; mt++) {
        float s0 = lsum0[mt], s1 = lsum1[mt];
        s0 += __shfl_xor_sync(0xffffffffu, s0, 1);
        s0 += __shfl_xor_sync(0xffffffffu, s0, 2);
        s1 += __shfl_xor_sync(0xffffffffu, s1, 1);
        s1 += __shfl_xor_sync(0xffffffffu, s1, 2);
        float inv0 = 1.f / s0, inv1 = 1.f / s1;
        const int grow = qb * 128 + r0 + 16 * mt;
        float* p0 = Out + hbase + (size_t)grow * 128 + (lane & 3) * 2;
        float* p1 = p0 + 8 * 128;
#pragma unroll
        for (int dt = 0; dt < 16; dt++) {
            *reinterpret_cast<float2*>(p0 + dt * 8) =
                make_float2(oacc[mt][dt][0] * inv0, oacc[mt][dt][1] * inv0);
            *reinterpret_cast<float2*>(p1 + dt * 8) =
                make_float2(oacc[mt][dt][2] * inv1, oacc[mt][dt][3] * inv1);
        }
    }
}

// ---------------------------------------------------------------------------
extern "C" void kernel_launch(void* const* d_in, const int* in_sizes, int n_in,
                              void* d_out, int out_size)
{
    const float* q    = reinterpret_cast<const float*>(d_in[0]);
    const float* k    = reinterpret_cast<const float*>(d_in[1]);
    const float* v    = reinterpret_cast<const float*>(d_in[2]);
    const int*   mask = reinterpret_cast<const int*>(d_in[3]);
    float* out = reinterpret_cast<float*>(d_out);

    cudaFuncSetAttribute(flash_mma_kernel, cudaFuncAttributeMaxDynamicSharedMemorySize, SMEM_B);

    pack_mask_kernel<<<512, 256>>>(mask);
    prep_q_kernel<<<NELEM / 4 / 256, 256>>>(reinterpret_cast<const float4*>(q));
    dim3 kvgrid(NELEM / 4 / 256, 2);
    prep_kv_kernel<<<kvgrid, 256>>>(reinterpret_cast<const float4*>(k),
                                    reinterpret_cast<const float4*>(v));

    dim3 grid(16, 64);
    flash_mma_kernel<<<grid, 128, SMEM_B>>>(out);
}

// round 16
// speedup vs baseline: 1.1526x; 1.0169x over previous
#include <cuda_runtime.h>
#include <cuda_fp16.h>
#include <cstdint>

#define NELEM 16777216            // 4*16*2048*128

// ---------------- global scratch (allocation-free) ----------------
__device__ __align__(16) uint32_t g_mask[2048 * 64];
__device__ __align__(16) __half g_qh[NELEM];
__device__ __align__(16) __half g_kh[NELEM];
__device__ __align__(16) __half g_vh[NELEM];

// ---------------- smem: persistent Q (128 rows) + 4-buffer K/V ring (64-row tiles)
#define ROWB 272                  // padded row stride in bytes (136 halves)
#define QBUF_B (128 * ROWB)       // 34816
#define KVB    (64 * ROWB)        // 17408 per 64x128 tile
#define SMEM_B (QBUF_B + 4 * KVB) // 104448 -> 2 CTAs/SM

// ---------------- helpers ----------------
__device__ __forceinline__ uint32_t smem_u32(const void* p) {
    uint32_t a;
    asm("{ .reg .u64 t; cvta.to.shared.u64 t, %1; cvt.u32.u64 %0, t; }" : "=r"(a) : "l"(p));
    return a;
}
__device__ __forceinline__ float ex2(float x) {
    float y; asm("ex2.approx.ftz.f32 %0, %1;" : "=f"(y) : "f"(x)); return y;
}
__device__ __forceinline__ uint32_t packh2(float x0, float x1) {
    __half2 h = __floats2half2_rn(x0, x1);
    return *reinterpret_cast<uint32_t*>(&h);
}
__device__ __forceinline__ void mma_f16(float* c, const uint32_t* a, const uint32_t* b) {
    asm volatile("mma.sync.aligned.m16n8k16.row.col.f32.f16.f16.f32 "
        "{%0,%1,%2,%3}, {%4,%5,%6,%7}, {%8,%9}, {%0,%1,%2,%3};"
        : "+f"(c[0]), "+f"(c[1]), "+f"(c[2]), "+f"(c[3])
        : "r"(a[0]), "r"(a[1]), "r"(a[2]), "r"(a[3]), "r"(b[0]), "r"(b[1]));
}
#define LDSM_X4(r, addr) \
    asm volatile("ldmatrix.sync.aligned.m8n8.x4.shared.b16 {%0,%1,%2,%3}, [%4];" \
        : "=r"((r)[0]), "=r"((r)[1]), "=r"((r)[2]), "=r"((r)[3]) : "r"(addr))
#define LDSM_X4T(r, addr) \
    asm volatile("ldmatrix.sync.aligned.m8n8.x4.trans.shared.b16 {%0,%1,%2,%3}, [%4];" \
        : "=r"((r)[0]), "=r"((r)[1]), "=r"((r)[2]), "=r"((r)[3]) : "r"(addr))
__device__ __forceinline__ void cpa16(uint32_t dst, const void* src) {
    asm volatile("cp.async.cg.shared.global [%0], [%1], 16;" :: "r"(dst), "l"(src) : "memory");
}
#define CP_COMMIT() asm volatile("cp.async.commit_group;" ::: "memory")
#define CP_WAIT(n)  asm volatile("cp.async.wait_group %0;" :: "n"(n) : "memory")

// padded byte offset for data uint4 index i (row = i>>4, col16 = i&15)
__device__ __forceinline__ uint32_t pad_off(int i) {
    return (uint32_t)(((i >> 4) * 17 + (i & 15)) * 16);
}

// ---------------- prep kernels ----------------
__global__ void pack_mask_kernel(const int* __restrict__ mask) {
    int w = blockIdx.x * blockDim.x + threadIdx.x;
    const int4* m4 = reinterpret_cast<const int4*>(mask) + (size_t)w * 8;
    uint32_t b = 0;
#pragma unroll
    for (int i = 0; i < 8; i++) {
        int4 v = m4[i];
        b |= (uint32_t)(v.x != 0) << (i * 4)     | (uint32_t)(v.y != 0) << (i * 4 + 1)
           | (uint32_t)(v.z != 0) << (i * 4 + 2) | (uint32_t)(v.w != 0) << (i * 4 + 3);
    }
    g_mask[w] = b;
}
__global__ void prep_q_kernel(const float4* __restrict__ q) {
    const float CS = 1.4426950408889634f / 11.313708498984761f;  // log2(e)/sqrt(128)
    int i = blockIdx.x * 256 + threadIdx.x;
    float4 x = q[i];
    reinterpret_cast<uint2*>(g_qh)[i] = make_uint2(packh2(x.x * CS, x.y * CS),
                                                   packh2(x.z * CS, x.w * CS));
}
__global__ void prep_kv_kernel(const float4* __restrict__ k, const float4* __restrict__ v) {
    int i = blockIdx.x * 256 + threadIdx.x;
    const float4* src = blockIdx.y ? v : k;
    __half* dst = blockIdx.y ? g_vh : g_kh;
    float4 x = src[i];
    reinterpret_cast<uint2*>(dst)[i] = make_uint2(packh2(x.x, x.y), packh2(x.z, x.w));
}

// ---------------- main kernel: grid(16, 64), 128 threads (4 warps x 32 rows) ------
__global__ void __launch_bounds__(128, 2)
flash_mma_kernel(float* __restrict__ Out)
{
    extern __shared__ __align__(16) char smp[];
    const uint32_t sbase = smem_u32(smp);
    const int tid = threadIdx.x, w = tid >> 5, lane = tid & 31;
    const int bh = blockIdx.y, qb = blockIdx.x;

    const size_t KV4 = 1024;                            // uint4 per 64x128 fp16 tile
    const size_t hbase4 = (size_t)bh * (KV4 * 32);      // 32 k-tiles per head
    const size_t qtile4 = (size_t)bh * 32768 + (size_t)qb * 2048;  // 128 Q rows

    const uint4* gq4 = reinterpret_cast<const uint4*>(g_qh);
    const uint4* gk4 = reinterpret_cast<const uint4*>(g_kh);
    const uint4* gv4 = reinterpret_cast<const uint4*>(g_vh);

    // ---- prologue: G0 = {Q, K0, V0} ; G1 = {K1, V1} ----
    for (int i = tid; i < 2048; i += 128)
        cpa16(sbase + pad_off(i), gq4 + qtile4 + i);
    for (int i = tid; i < 1024; i += 128) {
        uint32_t po = pad_off(i);
        cpa16(sbase + QBUF_B + 0 * KVB + po, gk4 + hbase4 + i);
        cpa16(sbase + QBUF_B + 1 * KVB + po, gv4 + hbase4 + i);
    }
    CP_COMMIT();
    for (int i = tid; i < 1024; i += 128) {
        uint32_t po = pad_off(i);
        cpa16(sbase + QBUF_B + 2 * KVB + po, gk4 + hbase4 + KV4 + i);
        cpa16(sbase + QBUF_B + 3 * KVB + po, gv4 + hbase4 + KV4 + i);
    }
    CP_COMMIT();

    float oacc[2][16][4];
    float lsum0[2], lsum1[2];
#pragma unroll
    for (int mt = 0; mt < 2; mt++) {
        lsum0[mt] = lsum1[mt] = 0.f;
#pragma unroll
        for (int i = 0; i < 16; i++)
            oacc[mt][i][0] = oacc[mt][i][1] = oacc[mt][i][2] = oacc[mt][i][3] = 0.f;
    }

    // per-thread ldmatrix base byte addresses
    const uint32_t aQ0 = sbase + (w * 32 + (lane & 15)) * ROWB + ((lane & 16) ? 16 : 0);
    const uint32_t bK  = ((lane >> 4) * 8 + (lane & 7)) * ROWB + ((lane & 8) ? 16 : 0);
    const uint32_t vVb = (lane & 15) * ROWB + ((lane >> 4) ? 16 : 0);

    const int shf = (lane & 3) * 2;
    const int r0 = w * 32 + (lane >> 2);                // mt=0 base row (local)
    const uint32_t* mbase = g_mask + (size_t)(qb * 128) * 64;

#pragma unroll 1
    for (int t = 0; t < 32; t++) {
        if (t == 31) { CP_WAIT(0); } else { CP_WAIT(1); }
        __syncthreads();    // K(t)/V(t) visible to all warps

        const uint32_t kcur = sbase + QBUF_B + (uint32_t)(2 * (t & 1)) * KVB;
        const uint32_t vcur = kcur + KVB;

        // ---- S-phase: S[32 x 64] per warp, Q A-frags reloaded from smem ----
        float sacc[2][8][4];
#pragma unroll
        for (int mt = 0; mt < 2; mt++)
#pragma unroll
            for (int j = 0; j < 8; j++)
                sacc[mt][j][0] = sacc[mt][j][1] = sacc[mt][j][2] = sacc[mt][j][3] = 0.f;
#pragma unroll
        for (int kt = 0; kt < 8; kt++) {
            uint32_t Qa[2][4];
            LDSM_X4(Qa[0], aQ0 + kt * 32);
            LDSM_X4(Qa[1], aQ0 + 16 * ROWB + kt * 32);
#pragma unroll
            for (int jS = 0; jS < 4; jS++) {
                uint32_t Bk[4];
                LDSM_X4(Bk, kcur + bK + jS * (16 * ROWB) + kt * 32);
                mma_f16(sacc[0][2 * jS],     Qa[0], Bk);
                mma_f16(sacc[0][2 * jS + 1], Qa[0], Bk + 2);
                mma_f16(sacc[1][2 * jS],     Qa[1], Bk);
                mma_f16(sacc[1][2 * jS + 1], Qa[1], Bk + 2);
            }
        }

        // ---- mask words (registers, reused across chunks) ----
        uint32_t mq[2][2][2];   // [mt][rowhalf][word]
#pragma unroll
        for (int mt = 0; mt < 2; mt++) {
            const int ra = r0 + 16 * mt;
            mq[mt][0][0] = __ldg(mbase + (size_t)ra * 64 + t * 2);
            mq[mt][0][1] = __ldg(mbase + (size_t)ra * 64 + t * 2 + 1);
            mq[mt][1][0] = __ldg(mbase + (size_t)(ra + 8) * 64 + t * 2);
            mq[mt][1][1] = __ldg(mbase + (size_t)(ra + 8) * 64 + t * 2 + 1);
        }

        // ---- fused convert + PV: chunk kt converted just before its MMAs ----
#pragma unroll
        for (int kt = 0; kt < 4; kt++) {
            uint32_t AHc[2][4];
#pragma unroll
            for (int mt = 0; mt < 2; mt++) {
                const int n0 = 2 * kt, n1 = 2 * kt + 1;
                uint32_t a0 = mq[mt][0][n0 >> 2] >> ((n0 & 3) * 8 + shf);
                uint32_t a1 = mq[mt][1][n0 >> 2] >> ((n0 & 3) * 8 + shf);
                uint32_t c0 = mq[mt][0][n1 >> 2] >> ((n1 & 3) * 8 + shf);
                uint32_t c1 = mq[mt][1][n1 >> 2] >> ((n1 & 3) * 8 + shf);
                float p0 = (a0 & 1u) ? ex2(sacc[mt][n0][0]) : 0.f;
                float p1 = (a0 & 2u) ? ex2(sacc[mt][n0][1]) : 0.f;
                float p2 = (a1 & 1u) ? ex2(sacc[mt][n0][2]) : 0.f;
                float p3 = (a1 & 2u) ? ex2(sacc[mt][n0][3]) : 0.f;
                float p4 = (c0 & 1u) ? ex2(sacc[mt][n1][0]) : 0.f;
                float p5 = (c0 & 2u) ? ex2(sacc[mt][n1][1]) : 0.f;
                float p6 = (c1 & 1u) ? ex2(sacc[mt][n1][2]) : 0.f;
                float p7 = (c1 & 2u) ? ex2(sacc[mt][n1][3]) : 0.f;
                lsum0[mt] += (p0 + p1) + (p4 + p5);
                lsum1[mt] += (p2 + p3) + (p6 + p7);
                AHc[mt][0] = packh2(p0, p1);
                AHc[mt][1] = packh2(p2, p3);
                AHc[mt][2] = packh2(p4, p5);
                AHc[mt][3] = packh2(p6, p7);
            }
#pragma unroll
            for (int jV = 0; jV < 8; jV++) {
                uint32_t Bv[4];
                LDSM_X4T(Bv, vcur + vVb + kt * (16 * ROWB) + jV * 32);
                mma_f16(oacc[0][2 * jV],     AHc[0], Bv);
                mma_f16(oacc[0][2 * jV + 1], AHc[0], Bv + 2);
                mma_f16(oacc[1][2 * jV],     AHc[1], Bv);
                mma_f16(oacc[1][2 * jV + 1], AHc[1], Bv + 2);
            }
        }

        __syncthreads();    // all warps done reading K(t)/V(t) before ring reuse
        if (t + 2 < 32) {   // prefetch K/V(t+2) into the buffers just freed
            const size_t toff = hbase4 + (size_t)(t + 2) * KV4;
            for (int i = tid; i < 1024; i += 128) {
                uint32_t po = pad_off(i);
                cpa16(kcur + po, gk4 + toff + i);
                cpa16(vcur + po, gv4 + toff + i);
            }
            CP_COMMIT();
        }
    }

    // ---- epilogue: quad-reduce row sums, normalize, store ----
    const size_t hbase = (size_t)bh * 262144;
#pragma unroll
    for (int mt = 0; mt < 2; mt++) {
        float s0 = lsum0[mt], s1 = lsum1[mt];
        s0 += __shfl_xor_sync(0xffffffffu, s0, 1);
        s0 += __shfl_xor_sync(0xffffffffu, s0, 2);
        s1 += __shfl_xor_sync(0xffffffffu, s1, 1);
        s1 += __shfl_xor_sync(0xffffffffu, s1, 2);
        float inv0 = 1.f / s0, inv1 = 1.f / s1;
        const int grow = qb * 128 + r0 + 16 * mt;
        float* p0 = Out + hbase + (size_t)grow * 128 + (lane & 3) * 2;
        float* p1 = p0 + 8 * 128;
#pragma unroll
        for (int dt = 0; dt < 16; dt++) {
            *reinterpret_cast<float2*>(p0 + dt * 8) =
                make_float2(oacc[mt][dt][0] * inv0, oacc[mt][dt][1] * inv0);
            *reinterpret_cast<float2*>(p1 + dt * 8) =
                make_float2(oacc[mt][dt][2] * inv1, oacc[mt][dt][3] * inv1);
        }
    }
}

// ---------------------------------------------------------------------------
extern "C" void kernel_launch(void* const* d_in, const int* in_sizes, int n_in,
                              void* d_out, int out_size)
{
    const float* q    = reinterpret_cast<const float*>(d_in[0]);
    const float* k    = reinterpret_cast<const float*>(d_in[1]);
    const float* v    = reinterpret_cast<const float*>(d_in[2]);
    const int*   mask = reinterpret_cast<const int*>(d_in[3]);
    float* out = reinterpret_cast<float*>(d_out);

    cudaFuncSetAttribute(flash_mma_kernel, cudaFuncAttributeMaxDynamicSharedMemorySize, SMEM_B);

    pack_mask_kernel<<<512, 256>>>(mask);
    prep_q_kernel<<<NELEM / 4 / 256, 256>>>(reinterpret_cast<const float4*>(q));
    dim3 kvgrid(NELEM / 4 / 256, 2);
    prep_kv_kernel<<<kvgrid, 256>>>(reinterpret_cast<const float4*>(k),
                                    reinterpret_cast<const float4*>(v));

    dim3 grid(16, 64);
    flash_mma_kernel<<<grid, 128, SMEM_B>>>(out);
}